// round 16
// baseline (speedup 1.0000x reference)
#include <cuda_runtime.h>
#include <cuda_bf16.h>
#include <cstdint>

// BundleAdjustmentModel: project N points into V=64 camera views.
// out[v][n] = (u,v);  cam = R_v p + t_v;  u = -f*x/sz + cx, v = f*y/sz + cy.
// HBM-write-bound (256 MB out).
// R16 = R14 with the pair-B store offset FIXED (+32 float4 = 64 points, was
// +16 = 32 points -> overlapping/missing writes, rel_err 1.1).
// Design: packed f32x2 math (PTX fma.rn.f32x2 -- FFMA2, ptxas won't emit it
// from C++). Each thread handles 4 points as TWO pairs banded 64 points
// apart, so each warp's two STG.128 per view are both fully contiguous 512B
// bursts (R7: warp store contiguity is load-bearing). Coefficients stored
// DUPLICATED in shared ([c,c] pairs) so ulonglong2 LDS.128 loads alias
// straight onto packed operand register pairs (no packing movs in mainloop).
// Prologue math EXACT (R12: fast-math trig amplifies through 1/z near Z_EPS).
// Folding:  A = -f*R0, tA = -f*tx ; B = f*R1, tB = f*ty ; C = R2, tC = -depth
// safe-z via clamp: 1/safe_z == clamp(1/z, -1/eps, +1/eps)

#define V_VIEWS 64
#define VG 8            // views per block
#define TPB 128         // 4 warps; block covers 512 points

typedef unsigned long long u64;

__device__ __forceinline__ u64 pack2(float lo, float hi) {
    u64 r; asm("mov.b64 %0, {%1, %2};" : "=l"(r) : "f"(lo), "f"(hi)); return r;
}
__device__ __forceinline__ void unpack2(u64 p, float& lo, float& hi) {
    asm("mov.b64 {%0, %1}, %2;" : "=f"(lo), "=f"(hi) : "l"(p));
}
__device__ __forceinline__ u64 fma2(u64 a, u64 b, u64 c) {
    u64 d; asm("fma.rn.f32x2 %0, %1, %2, %3;" : "=l"(d) : "l"(a), "l"(b), "l"(c));
    return d;
}

__global__ __launch_bounds__(TPB)
void bundle_project_kernel(const float* __restrict__ points,     // [N,3]
                           const float* __restrict__ euler,      // [V,3]
                           const float* __restrict__ txy,        // [V,2]
                           const float* __restrict__ tdepth,     // [V]
                           const float* __restrict__ focal_raw,  // [1]
                           const int*   __restrict__ cx_p,
                           const int*   __restrict__ cy_p,
                           float* __restrict__ out,              // [V,N,2]
                           int n_pts,
                           int chunks)
{
    // 24 floats/view, every coefficient duplicated: [Ax Ax Ay Ay Az Az Bx Bx
    //  By By Bz Bz Cx Cx Cy Cy Cz Cz tA tA tB tB tC tC]  (96B, 16B-aligned)
    __shared__ __align__(16) float sD[VG][24];
    __shared__ float s_cx, s_cy;

    const int tid   = threadIdx.x;
    const int chunk = blockIdx.x % chunks;
    const int vbase = (blockIdx.x / chunks) * VG;

    if (tid < VG) {
        const int v = vbase + tid;
        const float f = log1pf(expf(focal_raw[0])) + 50.0f;   // EXACT math only
        const float ex = euler[v * 3 + 0];
        const float ey = euler[v * 3 + 1];
        const float ez = euler[v * 3 + 2];
        float cxa = cosf(ex), sxa = sinf(ex);
        float cya = cosf(ey), sya = sinf(ey);
        float cza = cosf(ez), sza = sinf(ez);
        // R = Rx * Ry * Rz
        float R00 = cya * cza,                   R01 = -cya * sza,                  R02 = sya;
        float R10 = cxa * sza + sxa * sya * cza, R11 = cxa * cza - sxa * sya * sza, R12 = -sxa * cya;
        float R20 = sxa * sza - cxa * sya * cza, R21 = sxa * cza + cxa * sya * sza, R22 = cxa * cya;

        float vals[12];
        vals[0] = -f * R00;  vals[1] = -f * R01;  vals[2]  = -f * R02;
        vals[3] =  f * R10;  vals[4] =  f * R11;  vals[5]  =  f * R12;
        vals[6] =  R20;      vals[7] =  R21;      vals[8]  =  R22;
        vals[9]  = -f * txy[v * 2 + 0];
        vals[10] =  f * txy[v * 2 + 1];
        vals[11] = -(log1pf(expf(tdepth[v])) + 0.25f);
        #pragma unroll
        for (int j = 0; j < 12; j++) {
            sD[tid][2 * j + 0] = vals[j];
            sD[tid][2 * j + 1] = vals[j];
        }
    }
    if (tid == 0) {
        s_cx = (float)cx_p[0];
        s_cy = (float)cy_p[0];
    }
    __syncthreads();

    const int w = tid >> 5;
    const int l = tid & 31;
    // pair A: points nA, nA+1 ; pair B: 64 points later (second warp burst)
    const int nA = chunk * 512 + w * 128 + 2 * l;
    if (nA >= n_pts) return;
    const int nB = nA + 64;
    const bool fast = (nB + 1) < n_pts;            // all 4 points valid

    u64 pxA, pyA, pzA, pxB = 0, pyB = 0, pzB = 0;
    {
        const bool hasA2 = (nA + 1) < n_pts;
        float a0 = points[(size_t)nA * 3 + 0];
        float a1 = points[(size_t)nA * 3 + 1];
        float a2 = points[(size_t)nA * 3 + 2];
        float a3 = hasA2 ? points[(size_t)nA * 3 + 3] : 0.f;
        float a4 = hasA2 ? points[(size_t)nA * 3 + 4] : 0.f;
        float a5 = hasA2 ? points[(size_t)nA * 3 + 5] : 0.f;
        pxA = pack2(a0, a3); pyA = pack2(a1, a4); pzA = pack2(a2, a5);
        if (fast) {
            float b0 = points[(size_t)nB * 3 + 0];
            float b1 = points[(size_t)nB * 3 + 1];
            float b2 = points[(size_t)nB * 3 + 2];
            float b3 = points[(size_t)nB * 3 + 3];
            float b4 = points[(size_t)nB * 3 + 4];
            float b5 = points[(size_t)nB * 3 + 5];
            pxB = pack2(b0, b3); pyB = pack2(b1, b4); pzB = pack2(b2, b5);
        }
    }

    const u64 cx2 = pack2(s_cx, s_cx);
    const u64 cy2 = pack2(s_cy, s_cy);
    const float INV_CLAMP = 1.0f / 1e-4f;          // 1/Z_EPS
    const size_t view_stride = (size_t)n_pts * 2;  // floats per view slab

    float* baseA = out + ((size_t)vbase * n_pts + nA) * 2;

    #pragma unroll
    for (int v = 0; v < VG; v++) {
        const ulonglong2* cc = reinterpret_cast<const ulonglong2*>(&sD[v][0]);
        const ulonglong2 c0 = cc[0];   // Ax2 Ay2
        const ulonglong2 c1 = cc[1];   // Az2 Bx2
        const ulonglong2 c2 = cc[2];   // By2 Bz2
        const ulonglong2 c3 = cc[3];   // Cx2 Cy2
        const ulonglong2 c4 = cc[4];   // Cz2 tA2
        const ulonglong2 c5 = cc[5];   // tB2 tC2

        // ---- pair A ----
        u64 aA = fma2(c0.x, pxA, fma2(c0.y, pyA, fma2(c1.x, pzA, c4.y)));
        u64 bA = fma2(c1.y, pxA, fma2(c2.x, pyA, fma2(c2.y, pzA, c5.x)));
        u64 zA = fma2(c3.x, pxA, fma2(c3.y, pyA, fma2(c4.x, pzA, c5.y)));
        float z0, z1; unpack2(zA, z0, z1);
        float i0 = fminf(fmaxf(__fdividef(1.0f, z0), -INV_CLAMP), INV_CLAMP);
        float i1 = fminf(fmaxf(__fdividef(1.0f, z1), -INV_CLAMP), INV_CLAMP);
        u64 invA = pack2(i0, i1);
        u64 uA = fma2(aA, invA, cx2);
        u64 wA = fma2(bA, invA, cy2);
        float u0, u1, w0, w1;
        unpack2(uA, u0, u1); unpack2(wA, w0, w1);

        if (fast) {
            __stcs(reinterpret_cast<float4*>(baseA), make_float4(u0, w0, u1, w1));

            // ---- pair B ----
            u64 aB = fma2(c0.x, pxB, fma2(c0.y, pyB, fma2(c1.x, pzB, c4.y)));
            u64 bB = fma2(c1.y, pxB, fma2(c2.x, pyB, fma2(c2.y, pzB, c5.x)));
            u64 zB = fma2(c3.x, pxB, fma2(c3.y, pyB, fma2(c4.x, pzB, c5.y)));
            float z2, z3; unpack2(zB, z2, z3);
            float i2 = fminf(fmaxf(__fdividef(1.0f, z2), -INV_CLAMP), INV_CLAMP);
            float i3 = fminf(fmaxf(__fdividef(1.0f, z3), -INV_CLAMP), INV_CLAMP);
            u64 invB = pack2(i2, i3);
            u64 uB = fma2(aB, invB, cx2);
            u64 wB = fma2(bB, invB, cy2);
            float u2, u3, w2, w3;
            unpack2(uB, u2, u3); unpack2(wB, w2, w3);
            // pair B lives 64 points ahead = 128 floats = 32 float4 (FIXED)
            __stcs(reinterpret_cast<float4*>(baseA) + 32,
                   make_float4(u2, w2, u3, w3));
        } else {
            // tail: guarded per-point float2 stores (pair B invalid or absent)
            __stcs(reinterpret_cast<float2*>(baseA), make_float2(u0, w0));
            if (nA + 1 < n_pts)
                __stcs(reinterpret_cast<float2*>(baseA) + 1, make_float2(u1, w1));
        }
        baseA += view_stride;
    }
}

extern "C" void kernel_launch(void* const* d_in, const int* in_sizes, int n_in,
                              void* d_out, int out_size) {
    const float* points    = (const float*)d_in[0];
    const float* euler     = (const float*)d_in[1];
    const float* txy       = (const float*)d_in[2];
    const float* tdepth    = (const float*)d_in[3];
    const float* focal_raw = (const float*)d_in[4];
    const int*   cx_p      = (const int*)d_in[5];
    const int*   cy_p      = (const int*)d_in[6];
    float*       out       = (float*)d_out;

    const int n_pts = in_sizes[0] / 3;               // points is [N,3]
    const int chunks = (n_pts + 511) / 512;          // 512 points per block
    const int blocks = chunks * (V_VIEWS / VG);

    bundle_project_kernel<<<blocks, TPB>>>(points, euler, txy, tdepth,
                                           focal_raw, cx_p, cy_p,
                                           out, n_pts, chunks);
}